// round 12
// baseline (speedup 1.0000x reference)
#include <cuda_runtime.h>
#include <math.h>

#define NN 20000
#define EE 320000
#define ISQ3 0.57735026918962576f
#define ISQ2 0.70710678118654752f

typedef unsigned long long u64;

__device__ float g_Ssrc[NN*64];
__device__ float g_Sdst[NN*64];
__device__ float g_Vsrc[NN*96];   // [n][x*32+c]
__device__ float g_Vdst[NN*96];
__device__ float g_aex[EE*4];
__device__ unsigned int g_amax[NN*4];
__device__ float g_den[NN*4];
__device__ float g_agg[NN*160];   // per node: [h][16 hs + 24 hv]
__device__ float g_mid[(size_t)EE*160]; // per edge: ss0(32) ss1(32) v0(32) v1(32) v2(32)

__device__ __forceinline__ unsigned int fkey(float f) {
    unsigned int u = __float_as_uint(f);
    return (u & 0x80000000u) ? ~u : (u | 0x80000000u);
}
__device__ __forceinline__ float fdec(unsigned int k) {
    return __uint_as_float((k & 0x80000000u) ? (k ^ 0x80000000u) : ~k);
}
__device__ __forceinline__ float sigf(float x) { return 1.0f / (1.0f + expf(-x)); }

__device__ __forceinline__ u64 pack2(float a, float b) {
    u64 r; asm("mov.b64 %0,{%1,%2};" : "=l"(r) : "f"(a), "f"(b)); return r;
}
__device__ __forceinline__ u64 fma2(u64 a, u64 b, u64 c) {
    u64 d; asm("fma.rn.f32x2 %0,%1,%2,%3;" : "=l"(d) : "l"(a), "l"(b), "l"(c)); return d;
}
__device__ __forceinline__ void unpack2(u64 p, float& a, float& b) {
    asm("mov.b64 {%0,%1},%2;" : "=f"(a), "=f"(b) : "l"(p));
}

__global__ void k_init() {
    int st = gridDim.x * blockDim.x, t = blockIdx.x*blockDim.x + threadIdx.x;
    for (int i = t; i < NN*4; i += st) { g_amax[i] = 0u; g_den[i] = 0.f; }
    for (int i = t; i < NN*160; i += st) g_agg[i] = 0.f;
}

// ---- node norm + 4 linears: one warp per node ----
__global__ void __launch_bounds__(256) k_node(
    const float* __restrict__ node, const float* __restrict__ gs,
    const float* __restrict__ bs, const float* __restrict__ gv,
    const float* __restrict__ WsS, const float* __restrict__ WvS,
    const float* __restrict__ WsD, const float* __restrict__ WvD)
{
    int w = (blockIdx.x*blockDim.x + threadIdx.x) >> 5;
    int l = threadIdx.x & 31;
    if (w >= NN) return;
    const float* row = node + (size_t)w*160;
    float s0 = row[l], s1 = row[32+l];
    float sum = s0 + s1;
    #pragma unroll
    for (int o = 16; o >= 1; o >>= 1) sum += __shfl_xor_sync(~0u, sum, o);
    float mu = sum * (1.f/64.f);
    float d0 = s0-mu, d1 = s1-mu, vs = d0*d0 + d1*d1;
    #pragma unroll
    for (int o = 16; o >= 1; o >>= 1) vs += __shfl_xor_sync(~0u, vs, o);
    float inv = rsqrtf(vs*(1.f/64.f) + 1e-5f);
    float sn0 = d0*inv*gs[l] + bs[l];
    float sn1 = d1*inv*gs[32+l] + bs[32+l];
    float vx = row[64+3*l], vy = row[65+3*l], vz = row[66+3*l];
    float q = vx*vx + vy*vy + vz*vz;
    #pragma unroll
    for (int o = 16; o >= 1; o >>= 1) q += __shfl_xor_sync(~0u, q, o);
    float sc = gv[l] / sqrtf(q*(1.f/32.f) + 1e-5f);
    vx *= sc; vy *= sc; vz *= sc;
    float r0=0,r1=0,t0=0,t1=0;
    for (int c = 0; c < 32; c++) {
        float b = __shfl_sync(~0u, sn0, c);
        r0 += b*WsS[c*64+l]; r1 += b*WsS[c*64+32+l];
        t0 += b*WsD[c*64+l]; t1 += b*WsD[c*64+32+l];
    }
    for (int c = 0; c < 32; c++) {
        float b = __shfl_sync(~0u, sn1, c);
        r0 += b*WsS[(c+32)*64+l]; r1 += b*WsS[(c+32)*64+32+l];
        t0 += b*WsD[(c+32)*64+l]; t1 += b*WsD[(c+32)*64+32+l];
    }
    g_Ssrc[(size_t)w*64+l] = r0; g_Ssrc[(size_t)w*64+32+l] = r1;
    g_Sdst[(size_t)w*64+l] = t0; g_Sdst[(size_t)w*64+32+l] = t1;
    float a0=0,a1=0,a2=0,b0=0,b1=0,b2=0;
    for (int c = 0; c < 32; c++) {
        float wx = __shfl_sync(~0u, vx, c), wy = __shfl_sync(~0u, vy, c), wz = __shfl_sync(~0u, vz, c);
        float ws = WvS[c*32+l], wd = WvD[c*32+l];
        a0 += wx*ws; a1 += wy*ws; a2 += wz*ws;
        b0 += wx*wd; b1 += wy*wd; b2 += wz*wd;
    }
    float* VS = g_Vsrc + (size_t)w*96; float* VD = g_Vdst + (size_t)w*96;
    VS[l] = a0; VS[32+l] = a1; VS[64+l] = a2;
    VD[l] = b0; VD[32+l] = b1; VD[64+l] = b2;
}

#define E1STEP(cc,kk){ \
  float f0=__shfl_sync(~0u,rv0,(kk)), f1=__shfl_sync(~0u,rv0,16+(kk)); \
  float f2=__shfl_sync(~0u,rv1,(kk)), f3=__shfl_sync(~0u,rv1,16+(kk)); \
  wA[0]+=f0*a.cc; wA[1]+=f1*a.cc; wA[2]+=f2*a.cc; wA[3]+=f3*a.cc; \
  wB[0]+=f0*b.cc; wB[1]+=f1*b.cc; wB[2]+=f2*b.cc; wB[3]+=f3*b.cc; \
  wC[0]+=f0*c.cc; wC[1]+=f1*c.cc; wC[2]+=f2*c.cc; wC[3]+=f3*c.cc; }

// ---- edge pass 1: attention logits + segment max; warp per 4 edges ----
// smem (fl): WrT 224x20 @0 | WaP 32x196 @4480 | Ad 64 @10752 | staging 16x768 @10816
__global__ void __launch_bounds__(512) k_edge1(
    const int* __restrict__ ei, const float* __restrict__ rbf,
    const float* __restrict__ rsh, const float* __restrict__ Wr,
    const float* __restrict__ Wa, const float* __restrict__ ad)
{
    extern __shared__ float sm[];
    float* sWrT = sm; float* sWaP = sm+4480; float* sAd = sm+10752; float* sM = sm+10816;
    int tid = threadIdx.x;
    for (int i = tid; i < 3584; i += 512) { int b = i/224, c = i%224; sWrT[c*20+b] = Wr[i]; }
    for (int i = tid; i < 6144; i += 512) {
        int k = i/64, o = i%64;
        if (o < 32) sWaP[o*196 + 2*k] = Wa[i]; else sWaP[(o-32)*196 + 2*k + 1] = Wa[i];
    }
    if (tid < 64) sAd[tid] = ad[tid];
    __syncthreads();
    int l = tid & 31, wid = tid >> 5;
    float* mbase = sM + wid*768;
    int gw = blockIdx.x*16 + wid, tw = gridDim.x*16;
    for (int p = gw; p < EE/4; p += tw) {
        int e0 = 4*p;
        int src[4], dst[4]; float4 Y[4];
        #pragma unroll
        for (int u = 0; u < 4; u++) {
            src[u] = ei[e0+u]; dst[u] = ei[EE+e0+u];
            Y[u] = *(const float4*)&rsh[4*(e0+u)];
        }
        float rv0 = rbf[16*e0 + l], rv1 = rbf[16*e0 + 32 + l];
        float wA[4] = {0,0,0,0}, wB[4] = {0,0,0,0}, wC[4] = {0,0,0,0};
        #pragma unroll
        for (int q = 0; q < 4; q++) {
            float4 a = *(const float4*)&sWrT[l*20 + 4*q];
            float4 b = *(const float4*)&sWrT[(l+32)*20 + 4*q];
            float4 c = *(const float4*)&sWrT[(l+160)*20 + 4*q];
            E1STEP(x, 4*q) E1STEP(y, 4*q+1) E1STEP(z, 4*q+2) E1STEP(w, 4*q+3)
        }
        __syncwarp();
        #pragma unroll
        for (int u = 0; u < 4; u++) {
            float sc0 = g_Ssrc[src[u]*64+l]    + g_Sdst[dst[u]*64+l];
            float sc1 = g_Ssrc[src[u]*64+32+l] + g_Sdst[dst[u]*64+32+l];
            float vx = g_Vsrc[src[u]*96+l]    + g_Vdst[dst[u]*96+l];
            float vy = g_Vsrc[src[u]*96+32+l] + g_Vdst[dst[u]*96+32+l];
            float vz = g_Vsrc[src[u]*96+64+l] + g_Vdst[dst[u]*96+64+l];
            float ms0 = wA[u]*sc0*Y[u].x, ms1 = wB[u]*sc1*Y[u].x;
            float ms2 = wC[u]*(vx*Y[u].y + vy*Y[u].z + vz*Y[u].w)*ISQ3;
            float2* B = (float2*)(mbase + u*192);
            B[l] = make_float2(ms0, ms0); B[32+l] = make_float2(ms1, ms1); B[64+l] = make_float2(ms2, ms2);
        }
        __syncwarp();
        u64 acc0 = 0, acc1 = 0, acc2 = 0, acc3 = 0;
        const ulonglong2* wp = (const ulonglong2*)&sWaP[l*196];
        const ulonglong2* m0 = (const ulonglong2*)(mbase);
        const ulonglong2* m1 = (const ulonglong2*)(mbase+192);
        const ulonglong2* m2 = (const ulonglong2*)(mbase+384);
        const ulonglong2* m3 = (const ulonglong2*)(mbase+576);
        #pragma unroll 8
        for (int j = 0; j < 48; j++) {
            ulonglong2 w2 = wp[j];
            ulonglong2 a = m0[j], b = m1[j], c = m2[j], d = m3[j];
            acc0 = fma2(a.x, w2.x, acc0); acc0 = fma2(a.y, w2.y, acc0);
            acc1 = fma2(b.x, w2.x, acc1); acc1 = fma2(b.y, w2.y, acc1);
            acc2 = fma2(c.x, w2.x, acc2); acc2 = fma2(c.y, w2.y, acc2);
            acc3 = fma2(d.x, w2.x, acc3); acc3 = fma2(d.y, w2.y, acc3);
        }
        float aA[4], aB[4];
        unpack2(acc0, aA[0], aB[0]); unpack2(acc1, aA[1], aB[1]);
        unpack2(acc2, aA[2], aB[2]); unpack2(acc3, aA[3], aB[3]);
        #pragma unroll
        for (int u = 0; u < 4; u++) {
            aA[u] = aA[u] > 0.f ? aA[u] : 0.2f*aA[u];
            aB[u] = aB[u] > 0.f ? aB[u] : 0.2f*aB[u];
            aA[u] *= sAd[l]; aB[u] *= sAd[32+l];
        }
        #pragma unroll
        for (int o = 8; o >= 1; o >>= 1) {
            #pragma unroll
            for (int u = 0; u < 4; u++) {
                aA[u] += __shfl_xor_sync(~0u, aA[u], o, 16);
                aB[u] += __shfl_xor_sync(~0u, aB[u], o, 16);
            }
        }
        if (l == 0) {
            #pragma unroll
            for (int u = 0; u < 4; u++) {
                int e = e0+u, d = dst[u];
                g_aex[4*e] = aA[u]; g_aex[4*e+2] = aB[u];
                atomicMax(&g_amax[4*d],   fkey(aA[u]));
                atomicMax(&g_amax[4*d+2], fkey(aB[u]));
            }
        } else if (l == 16) {
            #pragma unroll
            for (int u = 0; u < 4; u++) {
                int e = e0+u, d = dst[u];
                g_aex[4*e+1] = aA[u]; g_aex[4*e+3] = aB[u];
                atomicMax(&g_amax[4*d+1], fkey(aA[u]));
                atomicMax(&g_amax[4*d+3], fkey(aB[u]));
            }
        }
    }
}

__global__ void k_soft(const int* __restrict__ ei) {
    int i = blockIdx.x*blockDim.x + threadIdx.x;
    if (i >= EE*4) return;
    int e = i >> 2, h = i & 3;
    int dst = ei[EE+e];
    float am = fdec(g_amax[4*dst+h]);
    if (!isfinite(am)) am = 0.f;
    float ex = expf(g_aex[i] - am);
    g_aex[i] = ex;
    atomicAdd(&g_den[4*dst+h], ex);
}

#define W1K(cc,kk){ \
  float f0=__shfl_sync(~0u,rv0,(kk)), f1=__shfl_sync(~0u,rv0,16+(kk)); \
  float f2=__shfl_sync(~0u,rv1,(kk)), f3=__shfl_sync(~0u,rv1,16+(kk)); \
  u64 wp01=pack2(A0.cc,A1.cc), wp23=pack2(A2.cc,A3.cc), wp46=pack2(A4.cc,A6.cc); \
  u64 md0=pack2(f0,f0), md1=pack2(f1,f1), md2=pack2(f2,f2), md3=pack2(f3,f3); \
  accw[0][0]=fma2(md0,wp01,accw[0][0]); accw[0][1]=fma2(md0,wp23,accw[0][1]); accw[0][2]=fma2(md0,wp46,accw[0][2]); acc5[0]+=f0*A5.cc; \
  accw[1][0]=fma2(md1,wp01,accw[1][0]); accw[1][1]=fma2(md1,wp23,accw[1][1]); accw[1][2]=fma2(md1,wp46,accw[1][2]); acc5[1]+=f1*A5.cc; \
  accw[2][0]=fma2(md2,wp01,accw[2][0]); accw[2][1]=fma2(md2,wp23,accw[2][1]); accw[2][2]=fma2(md2,wp46,accw[2][2]); acc5[2]+=f2*A5.cc; \
  accw[3][0]=fma2(md3,wp01,accw[3][0]); accw[3][1]=fma2(md3,wp23,accw[3][1]); accw[3][2]=fma2(md3,wp46,accw[3][2]); acc5[3]+=f3*A5.cc; }

// ---- edge pass 2a: w1 + gather + CG1 + val_s + gate + val_v -> g_mid ----
// 576 thr, 18 warps, warp per 4 edges (2 pairs)
// smem (fl): WrT 4480 @0 | WvalT 64x100 @4480 | WgT 32x68 @10880 | WvvT 32x132 @13056 |
//            staging 18x1920 @17280   total 51840 fl = 207360 B
__global__ void __launch_bounds__(576) k_edge2a(
    const int* __restrict__ ei, const float* __restrict__ rbf,
    const float* __restrict__ rsh, const float* __restrict__ Wr,
    const float* __restrict__ Wval, const float* __restrict__ Wvv,
    const float* __restrict__ Wg)
{
    extern __shared__ float sm[];
    float* sWrT   = sm;
    float* sWvalT = sm+4480;
    float* sWgT   = sm+10880;
    float* sWvvT  = sm+13056;
    float* sB     = sm+17280;
    int tid = threadIdx.x;
    for (int i = tid; i < 3584; i += 576) { int b = i/224, c = i%224; sWrT[c*20+b] = Wr[i]; }
    for (int i = tid; i < 6144; i += 576) { int k = i/64, o = i%64; sWvalT[o*100+k] = Wval[i]; }
    for (int i = tid; i < 2048; i += 576) { int k = i/32, o = i%32; sWgT[o*68+k] = Wg[i]; }
    for (int i = tid; i < 4096; i += 576) { int k = i/32, o = i%32; sWvvT[o*132+k] = Wvv[i]; }
    __syncthreads();
    int l = tid & 31, wid = tid >> 5;   // wid 0..17
    float* ebase = sB + wid*1920;
    int gw = blockIdx.x*18 + wid, tw = gridDim.x*18;
    for (int p = gw; p < EE/4; p += tw) {
        int e0 = 4*p;
        int src[4], dst[4]; float4 Y[4];
        #pragma unroll
        for (int u = 0; u < 4; u++) {
            src[u] = ei[e0+u]; dst[u] = ei[EE+e0+u];
            Y[u] = *(const float4*)&rsh[4*(e0+u)];
        }
        float rv0 = rbf[16*e0 + l], rv1 = rbf[16*e0 + 32 + l];
        // ---- w1 = rbf @ Wrbf (paired f32x2) ----
        u64 accw[4][3]; float acc5[4];
        #pragma unroll
        for (int u = 0; u < 4; u++) { accw[u][0]=0; accw[u][1]=0; accw[u][2]=0; acc5[u]=0.f; }
        #pragma unroll
        for (int q = 0; q < 4; q++) {
            float4 A0 = *(const float4*)&sWrT[(l      )*20 + 4*q];
            float4 A1 = *(const float4*)&sWrT[(l + 32 )*20 + 4*q];
            float4 A2 = *(const float4*)&sWrT[(l + 64 )*20 + 4*q];
            float4 A3 = *(const float4*)&sWrT[(l + 96 )*20 + 4*q];
            float4 A4 = *(const float4*)&sWrT[(l + 128)*20 + 4*q];
            float4 A5 = *(const float4*)&sWrT[(l + 160)*20 + 4*q];
            float4 A6 = *(const float4*)&sWrT[(l + 192)*20 + 4*q];
            W1K(x, 4*q) W1K(y, 4*q+1) W1K(z, 4*q+2) W1K(w, 4*q+3)
        }
        float w1[7][4];
        #pragma unroll
        for (int u = 0; u < 4; u++) {
            unpack2(accw[u][0], w1[0][u], w1[1][u]);
            unpack2(accw[u][1], w1[2][u], w1[3][u]);
            unpack2(accw[u][2], w1[4][u], w1[6][u]);
            w1[5][u] = acc5[u];
        }
        __syncwarp();
        // ---- stage 1: gather + CG product ----
        #pragma unroll
        for (int pr = 0; pr < 2; pr++) {
            int u0 = 2*pr, u1 = u0+1;
            float* pb = ebase + pr*960;
            float2* Bp  = (float2*)pb;
            float2* Cx0 = (float2*)(pb+192);
            float2* Cx1 = (float2*)(pb+448);
            float2* Czp = (float2*)(pb+704);
            float4 Ya = Y[u0], Yb = Y[u1];
            float sa0 = g_Ssrc[src[u0]*64+l]    + g_Sdst[dst[u0]*64+l];
            float sa1 = g_Ssrc[src[u0]*64+32+l] + g_Sdst[dst[u0]*64+32+l];
            float ax = g_Vsrc[src[u0]*96+l]    + g_Vdst[dst[u0]*96+l];
            float ay = g_Vsrc[src[u0]*96+32+l] + g_Vdst[dst[u0]*96+32+l];
            float az = g_Vsrc[src[u0]*96+64+l] + g_Vdst[dst[u0]*96+64+l];
            float sb0 = g_Ssrc[src[u1]*64+l]    + g_Sdst[dst[u1]*64+l];
            float sb1 = g_Ssrc[src[u1]*64+32+l] + g_Sdst[dst[u1]*64+32+l];
            float bx = g_Vsrc[src[u1]*96+l]    + g_Vdst[dst[u1]*96+l];
            float by = g_Vsrc[src[u1]*96+32+l] + g_Vdst[dst[u1]*96+32+l];
            float bz = g_Vsrc[src[u1]*96+64+l] + g_Vdst[dst[u1]*96+64+l];
            float cax = ay*Ya.w - az*Ya.z, cay = az*Ya.y - ax*Ya.w, caz = ax*Ya.z - ay*Ya.y;
            float cbx = by*Yb.w - bz*Yb.z, cby = bz*Yb.y - bx*Yb.w, cbz = bx*Yb.z - by*Yb.y;
            Bp[l]    = make_float2(w1[0][u0]*sa0*Ya.x, w1[0][u1]*sb0*Yb.x);
            Bp[32+l] = make_float2(w1[1][u0]*sa1*Ya.x, w1[1][u1]*sb1*Yb.x);
            Bp[64+l] = make_float2(w1[5][u0]*(ax*Ya.y+ay*Ya.z+az*Ya.w)*ISQ3,
                                   w1[5][u1]*(bx*Yb.y+by*Yb.z+bz*Yb.w)*ISQ3);
            float g2a = w1[2][u0]*sa0, g3a = w1[3][u0]*sa1, g4a = w1[4][u0], g6a = w1[6][u0]*ISQ2;
            float g2b = w1[2][u1]*sb0, g3b = w1[3][u1]*sb1, g4b = w1[4][u1], g6b = w1[6][u1]*ISQ2;
            Cx0[l]    = make_float2(g2a*Ya.y, g2a*Ya.z);
            Cx0[32+l] = make_float2(g3a*Ya.y, g3a*Ya.z);
            Cx0[64+l] = make_float2(g4a*ax*Ya.x, g4a*ay*Ya.x);
            Cx0[96+l] = make_float2(g6a*cax, g6a*cay);
            Cx1[l]    = make_float2(g2b*Yb.y, g2b*Yb.z);
            Cx1[32+l] = make_float2(g3b*Yb.y, g3b*Yb.z);
            Cx1[64+l] = make_float2(g4b*bx*Yb.x, g4b*by*Yb.x);
            Cx1[96+l] = make_float2(g6b*cbx, g6b*cby);
            Czp[l]    = make_float2(g2a*Ya.w,      g2b*Yb.w);
            Czp[32+l] = make_float2(g3a*Ya.w,      g3b*Yb.w);
            Czp[64+l] = make_float2(g4a*az*Ya.x,   g4b*bz*Yb.x);
            Czp[96+l] = make_float2(g6a*caz,       g6b*cbz);
        }
        __syncwarp();
        const ulonglong2* mp0 = (const ulonglong2*)(ebase);
        const ulonglong2* mp1 = (const ulonglong2*)(ebase+960);
        // ---- val_s (pre-sigmoid) ----
        float vs0[4], vs1[4];
        {
            u64 aA0=0, aB0=0, aA1=0, aB1=0;
            const float4* wa = (const float4*)&sWvalT[l*100];
            const float4* wb = (const float4*)&sWvalT[(32+l)*100];
            #pragma unroll 6
            for (int j = 0; j < 24; j++) {
                float4 a = wa[j], b = wb[j];
                ulonglong2 mA0 = mp0[2*j], mB0 = mp0[2*j+1];
                ulonglong2 mA1 = mp1[2*j], mB1 = mp1[2*j+1];
                u64 p0=pack2(a.x,a.x), p1=pack2(a.y,a.y), p2=pack2(a.z,a.z), p3=pack2(a.w,a.w);
                u64 q0=pack2(b.x,b.x), q1=pack2(b.y,b.y), q2=pack2(b.z,b.z), q3=pack2(b.w,b.w);
                aA0 = fma2(mA0.x,p0,aA0); aA0 = fma2(mA0.y,p1,aA0); aA0 = fma2(mB0.x,p2,aA0); aA0 = fma2(mB0.y,p3,aA0);
                aB0 = fma2(mA0.x,q0,aB0); aB0 = fma2(mA0.y,q1,aB0); aB0 = fma2(mB0.x,q2,aB0); aB0 = fma2(mB0.y,q3,aB0);
                aA1 = fma2(mA1.x,p0,aA1); aA1 = fma2(mA1.y,p1,aA1); aA1 = fma2(mB1.x,p2,aA1); aA1 = fma2(mB1.y,p3,aA1);
                aB1 = fma2(mA1.x,q0,aB1); aB1 = fma2(mA1.y,q1,aB1); aB1 = fma2(mB1.x,q2,aB1); aB1 = fma2(mB1.y,q3,aB1);
            }
            unpack2(aA0, vs0[0], vs0[1]); unpack2(aB0, vs1[0], vs1[1]);
            unpack2(aA1, vs0[2], vs0[3]); unpack2(aB1, vs1[2], vs1[3]);
        }
        __syncwarp();
        ((float2*)ebase)[l]        = make_float2(vs0[0], vs0[1]);
        ((float2*)ebase)[32+l]     = make_float2(vs1[0], vs1[1]);
        ((float2*)(ebase+960))[l]    = make_float2(vs0[2], vs0[3]);
        ((float2*)(ebase+960))[32+l] = make_float2(vs1[2], vs1[3]);
        __syncwarp();
        // ---- gate ----
        float gate[4];
        {
            u64 aG0 = 0, aG1 = 0;
            const float4* wg = (const float4*)&sWgT[l*68];
            #pragma unroll 4
            for (int j = 0; j < 16; j++) {
                float4 w = wg[j];
                ulonglong2 mA0 = mp0[2*j], mB0 = mp0[2*j+1];
                ulonglong2 mA1 = mp1[2*j], mB1 = mp1[2*j+1];
                u64 p0=pack2(w.x,w.x), p1=pack2(w.y,w.y), p2=pack2(w.z,w.z), p3=pack2(w.w,w.w);
                aG0 = fma2(mA0.x,p0,aG0); aG0 = fma2(mA0.y,p1,aG0); aG0 = fma2(mB0.x,p2,aG0); aG0 = fma2(mB0.y,p3,aG0);
                aG1 = fma2(mA1.x,p0,aG1); aG1 = fma2(mA1.y,p1,aG1); aG1 = fma2(mB1.x,p2,aG1); aG1 = fma2(mB1.y,p3,aG1);
            }
            float gE0,gE1,gE2,gE3;
            unpack2(aG0,gE0,gE1); unpack2(aG1,gE2,gE3);
            gate[0]=sigf(gE0); gate[1]=sigf(gE1); gate[2]=sigf(gE2); gate[3]=sigf(gE3);
        }
        // ---- val_v ----
        float v0[4], v1[4], v2[4];
        {
            u64 axy[4] = {0,0,0,0}; u64 az0 = 0, az1 = 0;
            const float4* wv = (const float4*)&sWvvT[l*132];
            const ulonglong2* cxA = (const ulonglong2*)(ebase+192);
            const ulonglong2* cxB = (const ulonglong2*)(ebase+448);
            const ulonglong2* cxC = (const ulonglong2*)(ebase+960+192);
            const ulonglong2* cxD = (const ulonglong2*)(ebase+960+448);
            const ulonglong2* czA = (const ulonglong2*)(ebase+704);
            const ulonglong2* czB = (const ulonglong2*)(ebase+960+704);
            #pragma unroll 4
            for (int j = 0; j < 32; j++) {
                float4 w = wv[j];
                u64 p0=pack2(w.x,w.x), p1=pack2(w.y,w.y), p2=pack2(w.z,w.z), p3=pack2(w.w,w.w);
                ulonglong2 a0 = cxA[2*j], a1 = cxA[2*j+1];
                axy[0] = fma2(a0.x,p0,axy[0]); axy[0] = fma2(a0.y,p1,axy[0]);
                axy[0] = fma2(a1.x,p2,axy[0]); axy[0] = fma2(a1.y,p3,axy[0]);
                ulonglong2 b0 = cxB[2*j], b1 = cxB[2*j+1];
                axy[1] = fma2(b0.x,p0,axy[1]); axy[1] = fma2(b0.y,p1,axy[1]);
                axy[1] = fma2(b1.x,p2,axy[1]); axy[1] = fma2(b1.y,p3,axy[1]);
                ulonglong2 c0 = cxC[2*j], c1 = cxC[2*j+1];
                axy[2] = fma2(c0.x,p0,axy[2]); axy[2] = fma2(c0.y,p1,axy[2]);
                axy[2] = fma2(c1.x,p2,axy[2]); axy[2] = fma2(c1.y,p3,axy[2]);
                ulonglong2 d0 = cxD[2*j], d1 = cxD[2*j+1];
                axy[3] = fma2(d0.x,p0,axy[3]); axy[3] = fma2(d0.y,p1,axy[3]);
                axy[3] = fma2(d1.x,p2,axy[3]); axy[3] = fma2(d1.y,p3,axy[3]);
                ulonglong2 z0 = czA[2*j], z1 = czA[2*j+1];
                az0 = fma2(z0.x,p0,az0); az0 = fma2(z0.y,p1,az0);
                az0 = fma2(z1.x,p2,az0); az0 = fma2(z1.y,p3,az0);
                ulonglong2 z2 = czB[2*j], z3 = czB[2*j+1];
                az1 = fma2(z2.x,p0,az1); az1 = fma2(z2.y,p1,az1);
                az1 = fma2(z3.x,p2,az1); az1 = fma2(z3.y,p3,az1);
            }
            #pragma unroll
            for (int u = 0; u < 4; u++) unpack2(axy[u], v0[u], v1[u]);
            unpack2(az0, v2[0], v2[1]); unpack2(az1, v2[2], v2[3]);
        }
        // ---- finalize: sigmoid + gate, write intermediate ----
        #pragma unroll
        for (int u = 0; u < 4; u++) {
            float* md = g_mid + (size_t)(e0+u)*160;
            md[l]      = sigf(vs0[u]);
            md[32+l]   = sigf(vs1[u]);
            md[64+l]   = v0[u]*gate[u];
            md[96+l]   = v1[u]*gate[u];
            md[128+l]  = v2[u]*gate[u];
        }
        __syncwarp();
    }
}

// ---- edge pass 2b: CG2 + hs + hv + scatter ----
// 640 thr, 20 warps, warp per 4 edges (2 pairs)
// smem (fl): WvlT 64x100 @0 | Wvv2T 32x132 @6400 | w2 224 @10624 | staging 20x1920 @10848
//            total 49248 fl = 196992 B
__global__ void __launch_bounds__(640) k_edge2b(
    const int* __restrict__ ei, const float* __restrict__ rsh,
    const float* __restrict__ w2ss, const float* __restrict__ w2sv,
    const float* __restrict__ w2vs, const float* __restrict__ w2v0,
    const float* __restrict__ w2v1,
    const float* __restrict__ Wvl, const float* __restrict__ Wvv2)
{
    extern __shared__ float sm[];
    float* sWvlT  = sm;
    float* sWvv2T = sm+6400;
    float* sw2    = sm+10624;
    float* sB     = sm+10848;
    int tid = threadIdx.x;
    for (int i = tid; i < 6144; i += 640) { int k = i/64, o = i%64; sWvlT[o*100+k] = Wvl[i]; }
    for (int i = tid; i < 4096; i += 640) { int k = i/32, o = i%32; sWvv2T[o*132+k] = Wvv2[i]; }
    if (tid < 64) { sw2[tid] = w2ss[tid]; sw2[64+tid] = w2sv[tid]; }
    if (tid < 32) { sw2[128+tid] = w2vs[tid]; sw2[160+tid] = w2v0[tid]; sw2[192+tid] = w2v1[tid]; }
    __syncthreads();
    int l = tid & 31, wid = tid >> 5;   // wid 0..19
    float* ebase = sB + wid*1920;
    int gw = blockIdx.x*20 + wid, tw = gridDim.x*20;
    for (int p = gw; p < EE/4; p += tw) {
        int e0 = 4*p;
        int dst[4]; float4 Y[4];
        float ss0[4], ss1[4], v0[4], v1[4], v2[4];
        #pragma unroll
        for (int u = 0; u < 4; u++) {
            dst[u] = ei[EE+e0+u];
            Y[u] = *(const float4*)&rsh[4*(e0+u)];
            const float* md = g_mid + (size_t)(e0+u)*160;
            ss0[u] = md[l]; ss1[u] = md[32+l];
            v0[u] = md[64+l]; v1[u] = md[96+l]; v2[u] = md[128+l];
        }
        // ---- CG2 staging ----
        #pragma unroll
        for (int pr = 0; pr < 2; pr++) {
            int u0 = 2*pr, u1 = u0+1;
            float* pb = ebase + pr*960;
            float2* Bp  = (float2*)pb;
            float2* Cx0 = (float2*)(pb+192);
            float2* Cx1 = (float2*)(pb+448);
            float2* Czp = (float2*)(pb+704);
            float4 Ya = Y[u0], Yb = Y[u1];
            float ssa = ss0[u0], sta = ss1[u0];
            float ssb = ss0[u1], stb = ss1[u1];
            float cax = v1[u0]*Ya.w - v2[u0]*Ya.z, cay = v2[u0]*Ya.y - v0[u0]*Ya.w, caz = v0[u0]*Ya.z - v1[u0]*Ya.y;
            float cbx = v1[u1]*Yb.w - v2[u1]*Yb.z, cby = v2[u1]*Yb.y - v0[u1]*Yb.w, cbz = v0[u1]*Yb.z - v1[u1]*Yb.y;
            Bp[l]    = make_float2(sw2[l]*ssa*Ya.x, sw2[l]*ssb*Yb.x);
            Bp[32+l] = make_float2(sw2[32+l]*sta*Ya.x, sw2[32+l]*stb*Yb.x);
            Bp[64+l] = make_float2(sw2[160+l]*(v0[u0]*Ya.y+v1[u0]*Ya.z+v2[u0]*Ya.w)*ISQ3,
                                   sw2[160+l]*(v0[u1]*Yb.y+v1[u1]*Yb.z+v2[u1]*Yb.w)*ISQ3);
            float g2a = sw2[64+l]*ssa, g3a = sw2[96+l]*sta, g4 = sw2[128+l], g6 = sw2[192+l]*ISQ2;
            float g2b = sw2[64+l]*ssb, g3b = sw2[96+l]*stb;
            Cx0[l]    = make_float2(g2a*Ya.y, g2a*Ya.z);
            Cx0[32+l] = make_float2(g3a*Ya.y, g3a*Ya.z);
            Cx0[64+l] = make_float2(g4*v0[u0]*Ya.x, g4*v1[u0]*Ya.x);
            Cx0[96+l] = make_float2(g6*cax, g6*cay);
            Cx1[l]    = make_float2(g2b*Yb.y, g2b*Yb.z);
            Cx1[32+l] = make_float2(g3b*Yb.y, g3b*Yb.z);
            Cx1[64+l] = make_float2(g4*v0[u1]*Yb.x, g4*v1[u1]*Yb.x);
            Cx1[96+l] = make_float2(g6*cbx, g6*cby);
            Czp[l]    = make_float2(g2a*Ya.w,        g2b*Yb.w);
            Czp[32+l] = make_float2(g3a*Ya.w,        g3b*Yb.w);
            Czp[64+l] = make_float2(g4*v2[u0]*Ya.x,  g4*v2[u1]*Yb.x);
            Czp[96+l] = make_float2(g6*caz,          g6*cbz);
        }
        __syncwarp();
        const ulonglong2* mp0 = (const ulonglong2*)(ebase);
        const ulonglong2* mp1 = (const ulonglong2*)(ebase+960);
        // ---- hs ----
        float hsA[4], hsB[4];
        {
            u64 aA0=0, aB0=0, aA1=0, aB1=0;
            const float4* wa = (const float4*)&sWvlT[l*100];
            const float4* wb = (const float4*)&sWvlT[(32+l)*100];
            #pragma unroll 6
            for (int j = 0; j < 24; j++) {
                float4 a = wa[j], b = wb[j];
                ulonglong2 mA0 = mp0[2*j], mB0 = mp0[2*j+1];
                ulonglong2 mA1 = mp1[2*j], mB1 = mp1[2*j+1];
                u64 p0=pack2(a.x,a.x), p1=pack2(a.y,a.y), p2=pack2(a.z,a.z), p3=pack2(a.w,a.w);
                u64 q0=pack2(b.x,b.x), q1=pack2(b.y,b.y), q2=pack2(b.z,b.z), q3=pack2(b.w,b.w);
                aA0 = fma2(mA0.x,p0,aA0); aA0 = fma2(mA0.y,p1,aA0); aA0 = fma2(mB0.x,p2,aA0); aA0 = fma2(mB0.y,p3,aA0);
                aB0 = fma2(mA0.x,q0,aB0); aB0 = fma2(mA0.y,q1,aB0); aB0 = fma2(mB0.x,q2,aB0); aB0 = fma2(mB0.y,q3,aB0);
                aA1 = fma2(mA1.x,p0,aA1); aA1 = fma2(mA1.y,p1,aA1); aA1 = fma2(mB1.x,p2,aA1); aA1 = fma2(mB1.y,p3,aA1);
                aB1 = fma2(mA1.x,q0,aB1); aB1 = fma2(mA1.y,q1,aB1); aB1 = fma2(mB1.x,q2,aB1); aB1 = fma2(mB1.y,q3,aB1);
            }
            unpack2(aA0, hsA[0], hsA[1]); unpack2(aB0, hsB[0], hsB[1]);
            unpack2(aA1, hsA[2], hsA[3]); unpack2(aB1, hsB[2], hsB[3]);
        }
        // ---- hv ----
        float h0[4], h1[4], h2[4];
        {
            u64 axy[4] = {0,0,0,0}; u64 az0 = 0, az1 = 0;
            const float4* wv = (const float4*)&sWvv2T[l*132];
            const ulonglong2* cxA = (const ulonglong2*)(ebase+192);
            const ulonglong2* cxB = (const ulonglong2*)(ebase+448);
            const ulonglong2* cxC = (const ulonglong2*)(ebase+960+192);
            const ulonglong2* cxD = (const ulonglong2*)(ebase+960+448);
            const ulonglong2* czA = (const ulonglong2*)(ebase+704);
            const ulonglong2* czB = (const ulonglong2*)(ebase+960+704);
            #pragma unroll 4
            for (int j = 0; j < 32; j++) {
                float4 w = wv[j];
                u64 p0=pack2(w.x,w.x), p1=pack2(w.y,w.y), p2=pack2(w.z,w.z), p3=pack2(w.w,w.w);
                ulonglong2 a0 = cxA[2*j], a1 = cxA[2*j+1];
                axy[0] = fma2(a0.x,p0,axy[0]); axy[0] = fma2(a0.y,p1,axy[0]);
                axy[0] = fma2(a1.x,p2,axy[0]); axy[0] = fma2(a1.y,p3,axy[0]);
                ulonglong2 b0 = cxB[2*j], b1 = cxB[2*j+1];
                axy[1] = fma2(b0.x,p0,axy[1]); axy[1] = fma2(b0.y,p1,axy[1]);
                axy[1] = fma2(b1.x,p2,axy[1]); axy[1] = fma2(b1.y,p3,axy[1]);
                ulonglong2 c0 = cxC[2*j], c1 = cxC[2*j+1];
                axy[2] = fma2(c0.x,p0,axy[2]); axy[2] = fma2(c0.y,p1,axy[2]);
                axy[2] = fma2(c1.x,p2,axy[2]); axy[2] = fma2(c1.y,p3,axy[2]);
                ulonglong2 d0 = cxD[2*j], d1 = cxD[2*j+1];
                axy[3] = fma2(d0.x,p0,axy[3]); axy[3] = fma2(d0.y,p1,axy[3]);
                axy[3] = fma2(d1.x,p2,axy[3]); axy[3] = fma2(d1.y,p3,axy[3]);
                ulonglong2 z0 = czA[2*j], z1 = czA[2*j+1];
                az0 = fma2(z0.x,p0,az0); az0 = fma2(z0.y,p1,az0);
                az0 = fma2(z1.x,p2,az0); az0 = fma2(z1.y,p3,az0);
                ulonglong2 z2 = czB[2*j], z3 = czB[2*j+1];
                az1 = fma2(z2.x,p0,az1); az1 = fma2(z2.y,p1,az1);
                az1 = fma2(z3.x,p2,az1); az1 = fma2(z3.y,p3,az1);
            }
            #pragma unroll
            for (int u = 0; u < 4; u++) unpack2(axy[u], h0[u], h1[u]);
            unpack2(az0, h2[0], h2[1]); unpack2(az1, h2[2], h2[3]);
        }
        // ---- attention weights & scatter ----
        int hA = l >> 4, hV = l >> 3;
        #pragma unroll
        for (int u = 0; u < 4; u++) {
            int e = e0+u, d = dst[u];
            float al0 = g_aex[4*e+hA]   / (g_den[4*d+hA]   + 1e-16f);
            float al1 = g_aex[4*e+2+hA] / (g_den[4*d+2+hA] + 1e-16f);
            float alv = g_aex[4*e+hV]   / (g_den[4*d+hV]   + 1e-16f);
            float* ag = g_agg + (size_t)d*160;
            atomicAdd(ag + hA*40 + (l&15), al0*hsA[u]);
            atomicAdd(ag + (2+hA)*40 + (l&15), al1*hsB[u]);
            int vb = hV*40 + 16 + (l&7)*3;
            atomicAdd(ag+vb,   alv*h0[u]);
            atomicAdd(ag+vb+1, alv*h1[u]);
            atomicAdd(ag+vb+2, alv*h2[u]);
        }
        __syncwarp();
    }
}

// ---- output projection + residual: warp per node ----
__global__ void __launch_bounds__(256) k_out(
    const float* __restrict__ node, const float* __restrict__ Wps,
    const float* __restrict__ Wpv, float* __restrict__ out)
{
    int w = (blockIdx.x*blockDim.x + threadIdx.x) >> 5;
    int l = threadIdx.x & 31;
    if (w >= NN) return;
    const float* ag = g_agg + (size_t)w*160;
    float a0 = ag[(l>>4)*40 + (l&15)];
    float a1 = ag[(2+(l>>4))*40 + (l&15)];
    int vb = (l>>3)*40 + 16 + (l&7)*3;
    float vx = ag[vb], vy = ag[vb+1], vz = ag[vb+2];
    float s0 = 0.f, s1 = 0.f;
    for (int c = 0; c < 32; c++) {
        float b = __shfl_sync(~0u, a0, c);
        s0 += b*Wps[c*64+l]; s1 += b*Wps[c*64+32+l];
    }
    for (int c = 0; c < 32; c++) {
        float b = __shfl_sync(~0u, a1, c);
        s0 += b*Wps[(c+32)*64+l]; s1 += b*Wps[(c+32)*64+32+l];
    }
    float o0 = 0.f, o1 = 0.f, o2 = 0.f;
    for (int c = 0; c < 32; c++) {
        float ww = Wpv[c*32+l];
        o0 += __shfl_sync(~0u, vx, c)*ww;
        o1 += __shfl_sync(~0u, vy, c)*ww;
        o2 += __shfl_sync(~0u, vz, c)*ww;
    }
    const float* nr = node + (size_t)w*160;
    float* orow = out + (size_t)w*160;
    orow[l] = nr[l] + s0;
    orow[32+l] = nr[32+l] + s1;
    orow[64+3*l] = nr[64+3*l] + o0;
    orow[65+3*l] = nr[65+3*l] + o1;
    orow[66+3*l] = nr[66+3*l] + o2;
}

extern "C" void kernel_launch(void* const* d_in, const int* in_sizes, int n_in,
                              void* d_out, int out_size) {
    int ei_pos = -1;
    for (int i = 0; i < n_in; i++) if (in_sizes[i] == 2*EE) { ei_pos = i; break; }
    const float* p[25]; int j = 0;
    for (int i = 0; i < n_in; i++) { if (i == ei_pos) continue; p[j++] = (const float*)d_in[i]; }
    const float *node = p[0], *rbf = p[1], *rsh = p[2], *gs = p[3], *bs = p[4], *gv = p[5],
                *WsS = p[6], *WvS = p[7], *WsD = p[8], *WvD = p[9], *Wr = p[10],
                *Wa = p[11], *ad = p[12], *Wval = p[13], *Wvv = p[14], *Wg = p[15],
                *w2ss = p[16], *w2sv = p[17], *w2vs = p[18], *w2v0 = p[19], *w2v1 = p[20],
                *Wvl = p[21], *Wvv2 = p[22], *Wps = p[23], *Wpv = p[24];
    const int* ei = (const int*)d_in[ei_pos];
    float* out = (float*)d_out;

    cudaFuncSetAttribute(k_edge1,  cudaFuncAttributeMaxDynamicSharedMemorySize, 23104*4);
    cudaFuncSetAttribute(k_edge2a, cudaFuncAttributeMaxDynamicSharedMemorySize, 51840*4);
    cudaFuncSetAttribute(k_edge2b, cudaFuncAttributeMaxDynamicSharedMemorySize, 49248*4);

    k_init<<<256, 256>>>();
    k_node<<<(NN*32 + 255)/256, 256>>>(node, gs, bs, gv, WsS, WvS, WsD, WvD);
    k_edge1<<<148, 512, 23104*4>>>(ei, rbf, rsh, Wr, Wa, ad);
    k_soft<<<(EE*4 + 255)/256, 256>>>(ei);
    k_edge2a<<<148, 576, 51840*4>>>(ei, rbf, rsh, Wr, Wval, Wvv, Wg);
    k_edge2b<<<148, 640, 49248*4>>>(ei, rsh, w2ss, w2sv, w2vs, w2v0, w2v1, Wvl, Wvv2);
    k_out<<<(NN*32 + 255)/256, 256>>>(node, Wps, Wpv, out);
}

// round 13
// speedup vs baseline: 1.0337x; 1.0337x over previous
#include <cuda_runtime.h>
#include <math.h>

#define NN 20000
#define EE 320000
#define ISQ3 0.57735026918962576f
#define ISQ2 0.70710678118654752f

typedef unsigned long long u64;

__device__ float g_Ssrc[NN*64];
__device__ float g_Sdst[NN*64];
__device__ float g_Vsrc[NN*96];   // [n][x*32+c]
__device__ float g_Vdst[NN*96];
__device__ float g_aex[EE*4];
__device__ unsigned int g_amax[NN*4];
__device__ float g_den[NN*4];
__device__ float g_agg[NN*160];   // per node: [h][16 hs + 24 hv]

__device__ __forceinline__ unsigned int fkey(float f) {
    unsigned int u = __float_as_uint(f);
    return (u & 0x80000000u) ? ~u : (u | 0x80000000u);
}
__device__ __forceinline__ float fdec(unsigned int k) {
    return __uint_as_float((k & 0x80000000u) ? (k ^ 0x80000000u) : ~k);
}
__device__ __forceinline__ float sigf(float x) { return 1.0f / (1.0f + expf(-x)); }

__device__ __forceinline__ u64 pack2(float a, float b) {
    u64 r; asm("mov.b64 %0,{%1,%2};" : "=l"(r) : "f"(a), "f"(b)); return r;
}
__device__ __forceinline__ u64 fma2(u64 a, u64 b, u64 c) {
    u64 d; asm("fma.rn.f32x2 %0,%1,%2,%3;" : "=l"(d) : "l"(a), "l"(b), "l"(c)); return d;
}
__device__ __forceinline__ void unpack2(u64 p, float& a, float& b) {
    asm("mov.b64 {%0,%1},%2;" : "=f"(a), "=f"(b) : "l"(p));
}

__global__ void k_init() {
    int st = gridDim.x * blockDim.x, t = blockIdx.x*blockDim.x + threadIdx.x;
    for (int i = t; i < NN*4; i += st) { g_amax[i] = 0u; g_den[i] = 0.f; }
    for (int i = t; i < NN*160; i += st) g_agg[i] = 0.f;
}

// ---- node norm + 4 linears: persistent, weights cached in smem ----
__global__ void __launch_bounds__(512) k_node(
    const float* __restrict__ node, const float* __restrict__ gs,
    const float* __restrict__ bs, const float* __restrict__ gv,
    const float* __restrict__ WsS, const float* __restrict__ WvS,
    const float* __restrict__ WsD, const float* __restrict__ WvD)
{
    __shared__ float sw[10240];   // WsS 4096 | WsD 4096 | WvS 1024 | WvD 1024
    float* sWsS = sw; float* sWsD = sw+4096; float* sWvS = sw+8192; float* sWvD = sw+9216;
    int tid = threadIdx.x;
    for (int i = tid; i < 4096; i += 512) { sWsS[i] = WsS[i]; sWsD[i] = WsD[i]; }
    for (int i = tid; i < 1024; i += 512) { sWvS[i] = WvS[i]; sWvD[i] = WvD[i]; }
    __syncthreads();
    int l = tid & 31, wid = tid >> 5;
    int tw = gridDim.x*16;
    for (int w = blockIdx.x*16 + wid; w < NN; w += tw) {
        const float* row = node + (size_t)w*160;
        float s0 = row[l], s1 = row[32+l];
        float sum = s0 + s1;
        #pragma unroll
        for (int o = 16; o >= 1; o >>= 1) sum += __shfl_xor_sync(~0u, sum, o);
        float mu = sum * (1.f/64.f);
        float d0 = s0-mu, d1 = s1-mu, vs = d0*d0 + d1*d1;
        #pragma unroll
        for (int o = 16; o >= 1; o >>= 1) vs += __shfl_xor_sync(~0u, vs, o);
        float inv = rsqrtf(vs*(1.f/64.f) + 1e-5f);
        float sn0 = d0*inv*gs[l] + bs[l];
        float sn1 = d1*inv*gs[32+l] + bs[32+l];
        float vx = row[64+3*l], vy = row[65+3*l], vz = row[66+3*l];
        float q = vx*vx + vy*vy + vz*vz;
        #pragma unroll
        for (int o = 16; o >= 1; o >>= 1) q += __shfl_xor_sync(~0u, q, o);
        float sc = gv[l] / sqrtf(q*(1.f/32.f) + 1e-5f);
        vx *= sc; vy *= sc; vz *= sc;
        float r0=0,r1=0,t0=0,t1=0;
        for (int c = 0; c < 32; c++) {
            float b = __shfl_sync(~0u, sn0, c);
            r0 += b*sWsS[c*64+l]; r1 += b*sWsS[c*64+32+l];
            t0 += b*sWsD[c*64+l]; t1 += b*sWsD[c*64+32+l];
        }
        for (int c = 0; c < 32; c++) {
            float b = __shfl_sync(~0u, sn1, c);
            r0 += b*sWsS[(c+32)*64+l]; r1 += b*sWsS[(c+32)*64+32+l];
            t0 += b*sWsD[(c+32)*64+l]; t1 += b*sWsD[(c+32)*64+32+l];
        }
        g_Ssrc[(size_t)w*64+l] = r0; g_Ssrc[(size_t)w*64+32+l] = r1;
        g_Sdst[(size_t)w*64+l] = t0; g_Sdst[(size_t)w*64+32+l] = t1;
        float a0=0,a1=0,a2=0,b0=0,b1=0,b2=0;
        for (int c = 0; c < 32; c++) {
            float wx = __shfl_sync(~0u, vx, c), wy = __shfl_sync(~0u, vy, c), wz = __shfl_sync(~0u, vz, c);
            float ws = sWvS[c*32+l], wd = sWvD[c*32+l];
            a0 += wx*ws; a1 += wy*ws; a2 += wz*ws;
            b0 += wx*wd; b1 += wy*wd; b2 += wz*wd;
        }
        float* VS = g_Vsrc + (size_t)w*96; float* VD = g_Vdst + (size_t)w*96;
        VS[l] = a0; VS[32+l] = a1; VS[64+l] = a2;
        VD[l] = b0; VD[32+l] = b1; VD[64+l] = b2;
    }
}

#define E1STEP(cc,kk){ \
  float f0=__shfl_sync(~0u,rv0,(kk)), f1=__shfl_sync(~0u,rv0,16+(kk)); \
  float f2=__shfl_sync(~0u,rv1,(kk)), f3=__shfl_sync(~0u,rv1,16+(kk)); \
  wA[0]+=f0*a.cc; wA[1]+=f1*a.cc; wA[2]+=f2*a.cc; wA[3]+=f3*a.cc; \
  wB[0]+=f0*b.cc; wB[1]+=f1*b.cc; wB[2]+=f2*b.cc; wB[3]+=f3*b.cc; \
  wC[0]+=f0*c.cc; wC[1]+=f1*c.cc; wC[2]+=f2*c.cc; wC[3]+=f3*c.cc; }

// ---- edge pass 1: attention logits + segment max; warp per 4 edges ----
__global__ void __launch_bounds__(512) k_edge1(
    const int* __restrict__ ei, const float* __restrict__ rbf,
    const float* __restrict__ rsh, const float* __restrict__ Wr,
    const float* __restrict__ Wa, const float* __restrict__ ad)
{
    extern __shared__ float sm[];
    float* sWrT = sm; float* sWaP = sm+4480; float* sAd = sm+10752; float* sM = sm+10816;
    int tid = threadIdx.x;
    for (int i = tid; i < 3584; i += 512) { int b = i/224, c = i%224; sWrT[c*20+b] = Wr[i]; }
    for (int i = tid; i < 6144; i += 512) {
        int k = i/64, o = i%64;
        if (o < 32) sWaP[o*196 + 2*k] = Wa[i]; else sWaP[(o-32)*196 + 2*k + 1] = Wa[i];
    }
    if (tid < 64) sAd[tid] = ad[tid];
    __syncthreads();
    int l = tid & 31, wid = tid >> 5;
    float* mbase = sM + wid*768;
    int gw = blockIdx.x*16 + wid, tw = gridDim.x*16;
    for (int p = gw; p < EE/4; p += tw) {
        int e0 = 4*p;
        int src[4], dst[4]; float4 Y[4];
        #pragma unroll
        for (int u = 0; u < 4; u++) {
            src[u] = ei[e0+u]; dst[u] = ei[EE+e0+u];
            Y[u] = *(const float4*)&rsh[4*(e0+u)];
        }
        float rv0 = rbf[16*e0 + l], rv1 = rbf[16*e0 + 32 + l];
        float wA[4] = {0,0,0,0}, wB[4] = {0,0,0,0}, wC[4] = {0,0,0,0};
        #pragma unroll
        for (int q = 0; q < 4; q++) {
            float4 a = *(const float4*)&sWrT[l*20 + 4*q];
            float4 b = *(const float4*)&sWrT[(l+32)*20 + 4*q];
            float4 c = *(const float4*)&sWrT[(l+160)*20 + 4*q];
            E1STEP(x, 4*q) E1STEP(y, 4*q+1) E1STEP(z, 4*q+2) E1STEP(w, 4*q+3)
        }
        __syncwarp();
        #pragma unroll
        for (int u = 0; u < 4; u++) {
            float sc0 = g_Ssrc[src[u]*64+l]    + g_Sdst[dst[u]*64+l];
            float sc1 = g_Ssrc[src[u]*64+32+l] + g_Sdst[dst[u]*64+32+l];
            float vx = g_Vsrc[src[u]*96+l]    + g_Vdst[dst[u]*96+l];
            float vy = g_Vsrc[src[u]*96+32+l] + g_Vdst[dst[u]*96+32+l];
            float vz = g_Vsrc[src[u]*96+64+l] + g_Vdst[dst[u]*96+64+l];
            float ms0 = wA[u]*sc0*Y[u].x, ms1 = wB[u]*sc1*Y[u].x;
            float ms2 = wC[u]*(vx*Y[u].y + vy*Y[u].z + vz*Y[u].w)*ISQ3;
            float2* B = (float2*)(mbase + u*192);
            B[l] = make_float2(ms0, ms0); B[32+l] = make_float2(ms1, ms1); B[64+l] = make_float2(ms2, ms2);
        }
        __syncwarp();
        u64 acc0 = 0, acc1 = 0, acc2 = 0, acc3 = 0;
        const ulonglong2* wp = (const ulonglong2*)&sWaP[l*196];
        const ulonglong2* m0 = (const ulonglong2*)(mbase);
        const ulonglong2* m1 = (const ulonglong2*)(mbase+192);
        const ulonglong2* m2 = (const ulonglong2*)(mbase+384);
        const ulonglong2* m3 = (const ulonglong2*)(mbase+576);
        #pragma unroll 8
        for (int j = 0; j < 48; j++) {
            ulonglong2 w2 = wp[j];
            ulonglong2 a = m0[j], b = m1[j], c = m2[j], d = m3[j];
            acc0 = fma2(a.x, w2.x, acc0); acc0 = fma2(a.y, w2.y, acc0);
            acc1 = fma2(b.x, w2.x, acc1); acc1 = fma2(b.y, w2.y, acc1);
            acc2 = fma2(c.x, w2.x, acc2); acc2 = fma2(c.y, w2.y, acc2);
            acc3 = fma2(d.x, w2.x, acc3); acc3 = fma2(d.y, w2.y, acc3);
        }
        float aA[4], aB[4];
        unpack2(acc0, aA[0], aB[0]); unpack2(acc1, aA[1], aB[1]);
        unpack2(acc2, aA[2], aB[2]); unpack2(acc3, aA[3], aB[3]);
        #pragma unroll
        for (int u = 0; u < 4; u++) {
            aA[u] = aA[u] > 0.f ? aA[u] : 0.2f*aA[u];
            aB[u] = aB[u] > 0.f ? aB[u] : 0.2f*aB[u];
            aA[u] *= sAd[l]; aB[u] *= sAd[32+l];
        }
        #pragma unroll
        for (int o = 8; o >= 1; o >>= 1) {
            #pragma unroll
            for (int u = 0; u < 4; u++) {
                aA[u] += __shfl_xor_sync(~0u, aA[u], o, 16);
                aB[u] += __shfl_xor_sync(~0u, aB[u], o, 16);
            }
        }
        if (l == 0) {
            #pragma unroll
            for (int u = 0; u < 4; u++) {
                int e = e0+u, d = dst[u];
                g_aex[4*e] = aA[u]; g_aex[4*e+2] = aB[u];
                atomicMax(&g_amax[4*d],   fkey(aA[u]));
                atomicMax(&g_amax[4*d+2], fkey(aB[u]));
            }
        } else if (l == 16) {
            #pragma unroll
            for (int u = 0; u < 4; u++) {
                int e = e0+u, d = dst[u];
                g_aex[4*e+1] = aA[u]; g_aex[4*e+3] = aB[u];
                atomicMax(&g_amax[4*d+1], fkey(aA[u]));
                atomicMax(&g_amax[4*d+3], fkey(aB[u]));
            }
        }
    }
}

__global__ void k_soft(const int* __restrict__ ei) {
    int i = blockIdx.x*blockDim.x + threadIdx.x;
    if (i >= EE*4) return;
    int e = i >> 2, h = i & 3;
    int dst = ei[EE+e];
    float am = fdec(g_amax[4*dst+h]);
    if (!isfinite(am)) am = 0.f;
    float ex = expf(g_aex[i] - am);
    g_aex[i] = ex;
    atomicAdd(&g_den[4*dst+h], ex);
}

#define W1K(cc,kk){ \
  float f0=__shfl_sync(~0u,rv0,(kk)), f1=__shfl_sync(~0u,rv0,16+(kk)); \
  float f2=__shfl_sync(~0u,rv1,(kk)), f3=__shfl_sync(~0u,rv1,16+(kk)); \
  u64 wp01=pack2(A0.cc,A1.cc), wp23=pack2(A2.cc,A3.cc), wp46=pack2(A4.cc,A6.cc); \
  u64 md0=pack2(f0,f0), md1=pack2(f1,f1), md2=pack2(f2,f2), md3=pack2(f3,f3); \
  accw[0][0]=fma2(md0,wp01,accw[0][0]); accw[0][1]=fma2(md0,wp23,accw[0][1]); accw[0][2]=fma2(md0,wp46,accw[0][2]); acc5[0]+=f0*A5.cc; \
  accw[1][0]=fma2(md1,wp01,accw[1][0]); accw[1][1]=fma2(md1,wp23,accw[1][1]); accw[1][2]=fma2(md1,wp46,accw[1][2]); acc5[1]+=f1*A5.cc; \
  accw[2][0]=fma2(md2,wp01,accw[2][0]); accw[2][1]=fma2(md2,wp23,accw[2][1]); accw[2][2]=fma2(md2,wp46,accw[2][2]); acc5[2]+=f2*A5.cc; \
  accw[3][0]=fma2(md3,wp01,accw[3][0]); accw[3][1]=fma2(md3,wp23,accw[3][1]); accw[3][2]=fma2(md3,wp46,accw[3][2]); acc5[3]+=f3*A5.cc; }

// ---- edge pass 2: value path + scatter; 448 thr, warp per 4 edges (2 pairs) ----
__global__ void __launch_bounds__(448) k_edge2(
    const int* __restrict__ ei, const float* __restrict__ rbf,
    const float* __restrict__ rsh, const float* __restrict__ Wr,
    const float* __restrict__ Wval, const float* __restrict__ Wvv,
    const float* __restrict__ Wg,
    const float* __restrict__ w2ss, const float* __restrict__ w2sv,
    const float* __restrict__ w2vs, const float* __restrict__ w2v0,
    const float* __restrict__ w2v1,
    const float* __restrict__ Wvl, const float* __restrict__ Wvv2)
{
    extern __shared__ float sm[];
    float* sWrT   = sm;
    float* sWvalT = sm+4480;
    float* sWgT   = sm+10880;
    float* sWvvT  = sm+13056;
    float* sWvlT  = sm+17280;
    float* sWvv2T = sm+23680;
    float* sw2    = sm+27904;
    float* sB     = sm+28128;
    int tid = threadIdx.x;
    for (int i = tid; i < 3584; i += 448) { int b = i/224, c = i%224; sWrT[c*20+b] = Wr[i]; }
    for (int i = tid; i < 6144; i += 448) { int k = i/64, o = i%64; sWvalT[o*100+k] = Wval[i]; sWvlT[o*100+k] = Wvl[i]; }
    for (int i = tid; i < 2048; i += 448) { int k = i/32, o = i%32; sWgT[o*68+k] = Wg[i]; }
    for (int i = tid; i < 4096; i += 448) { int k = i/32, o = i%32; sWvvT[o*132+k] = Wvv[i]; sWvv2T[o*132+k] = Wvv2[i]; }
    if (tid < 64) { sw2[tid] = w2ss[tid]; sw2[64+tid] = w2sv[tid]; }
    if (tid < 32) { sw2[128+tid] = w2vs[tid]; sw2[160+tid] = w2v0[tid]; sw2[192+tid] = w2v1[tid]; }
    __syncthreads();
    int l = tid & 31, wid = tid >> 5;   // wid 0..13
    float* ebase = sB + wid*1920;
    int gw = blockIdx.x*14 + wid, tw = gridDim.x*14;
    for (int p = gw; p < EE/4; p += tw) {
        int e0 = 4*p;
        int src[4], dst[4]; float4 Y[4];
        #pragma unroll
        for (int u = 0; u < 4; u++) {
            src[u] = ei[e0+u]; dst[u] = ei[EE+e0+u];
            Y[u] = *(const float4*)&rsh[4*(e0+u)];
        }
        float rv0 = rbf[16*e0 + l], rv1 = rbf[16*e0 + 32 + l];
        u64 accw[4][3]; float acc5[4];
        #pragma unroll
        for (int u = 0; u < 4; u++) { accw[u][0]=0; accw[u][1]=0; accw[u][2]=0; acc5[u]=0.f; }
        #pragma unroll
        for (int q = 0; q < 4; q++) {
            float4 A0 = *(const float4*)&sWrT[(l      )*20 + 4*q];
            float4 A1 = *(const float4*)&sWrT[(l + 32 )*20 + 4*q];
            float4 A2 = *(const float4*)&sWrT[(l + 64 )*20 + 4*q];
            float4 A3 = *(const float4*)&sWrT[(l + 96 )*20 + 4*q];
            float4 A4 = *(const float4*)&sWrT[(l + 128)*20 + 4*q];
            float4 A5 = *(const float4*)&sWrT[(l + 160)*20 + 4*q];
            float4 A6 = *(const float4*)&sWrT[(l + 192)*20 + 4*q];
            W1K(x, 4*q) W1K(y, 4*q+1) W1K(z, 4*q+2) W1K(w, 4*q+3)
        }
        float w1[7][4];
        #pragma unroll
        for (int u = 0; u < 4; u++) {
            unpack2(accw[u][0], w1[0][u], w1[1][u]);
            unpack2(accw[u][1], w1[2][u], w1[3][u]);
            unpack2(accw[u][2], w1[4][u], w1[6][u]);
            w1[5][u] = acc5[u];
        }
        __syncwarp();
        #pragma unroll
        for (int pr = 0; pr < 2; pr++) {
            int u0 = 2*pr, u1 = u0+1;
            float* pb = ebase + pr*960;
            float2* Bp  = (float2*)pb;
            float2* Cx0 = (float2*)(pb+192);
            float2* Cx1 = (float2*)(pb+448);
            float2* Czp = (float2*)(pb+704);
            float4 Ya = Y[u0], Yb = Y[u1];
            float sa0 = g_Ssrc[src[u0]*64+l]    + g_Sdst[dst[u0]*64+l];
            float sa1 = g_Ssrc[src[u0]*64+32+l] + g_Sdst[dst[u0]*64+32+l];
            float ax = g_Vsrc[src[u0]*96+l]    + g_Vdst[dst[u0]*96+l];
            float ay = g_Vsrc[src[u0]*96+32+l] + g_Vdst[dst[u0]*96+32+l];
            float az = g_Vsrc[src[u0]*96+64+l] + g_Vdst[dst[u0]*96+64+l];
            float sb0 = g_Ssrc[src[u1]*64+l]    + g_Sdst[dst[u1]*64+l];
            float sb1 = g_Ssrc[src[u1]*64+32+l] + g_Sdst[dst[u1]*64+32+l];
            float bx = g_Vsrc[src[u1]*96+l]    + g_Vdst[dst[u1]*96+l];
            float by = g_Vsrc[src[u1]*96+32+l] + g_Vdst[dst[u1]*96+32+l];
            float bz = g_Vsrc[src[u1]*96+64+l] + g_Vdst[dst[u1]*96+64+l];
            float cax = ay*Ya.w - az*Ya.z, cay = az*Ya.y - ax*Ya.w, caz = ax*Ya.z - ay*Ya.y;
            float cbx = by*Yb.w - bz*Yb.z, cby = bz*Yb.y - bx*Yb.w, cbz = bx*Yb.z - by*Yb.y;
            Bp[l]    = make_float2(w1[0][u0]*sa0*Ya.x, w1[0][u1]*sb0*Yb.x);
            Bp[32+l] = make_float2(w1[1][u0]*sa1*Ya.x, w1[1][u1]*sb1*Yb.x);
            Bp[64+l] = make_float2(w1[5][u0]*(ax*Ya.y+ay*Ya.z+az*Ya.w)*ISQ3,
                                   w1[5][u1]*(bx*Yb.y+by*Yb.z+bz*Yb.w)*ISQ3);
            float g2a = w1[2][u0]*sa0, g3a = w1[3][u0]*sa1, g4a = w1[4][u0], g6a = w1[6][u0]*ISQ2;
            float g2b = w1[2][u1]*sb0, g3b = w1[3][u1]*sb1, g4b = w1[4][u1], g6b = w1[6][u1]*ISQ2;
            Cx0[l]    = make_float2(g2a*Ya.y, g2a*Ya.z);
            Cx0[32+l] = make_float2(g3a*Ya.y, g3a*Ya.z);
            Cx0[64+l] = make_float2(g4a*ax*Ya.x, g4a*ay*Ya.x);
            Cx0[96+l] = make_float2(g6a*cax, g6a*cay);
            Cx1[l]    = make_float2(g2b*Yb.y, g2b*Yb.z);
            Cx1[32+l] = make_float2(g3b*Yb.y, g3b*Yb.z);
            Cx1[64+l] = make_float2(g4b*bx*Yb.x, g4b*by*Yb.x);
            Cx1[96+l] = make_float2(g6b*cbx, g6b*cby);
            Czp[l]    = make_float2(g2a*Ya.w,      g2b*Yb.w);
            Czp[32+l] = make_float2(g3a*Ya.w,      g3b*Yb.w);
            Czp[64+l] = make_float2(g4a*az*Ya.x,   g4b*bz*Yb.x);
            Czp[96+l] = make_float2(g6a*caz,       g6b*cbz);
        }
        __syncwarp();
        const ulonglong2* mp0 = (const ulonglong2*)(ebase);
        const ulonglong2* mp1 = (const ulonglong2*)(ebase+960);
        float vs0[4], vs1[4];
        {
            u64 aA0=0, aB0=0, aA1=0, aB1=0;
            const float4* wa = (const float4*)&sWvalT[l*100];
            const float4* wb = (const float4*)&sWvalT[(32+l)*100];
            #pragma unroll 6
            for (int j = 0; j < 24; j++) {
                float4 a = wa[j], b = wb[j];
                ulonglong2 mA0 = mp0[2*j], mB0 = mp0[2*j+1];
                ulonglong2 mA1 = mp1[2*j], mB1 = mp1[2*j+1];
                u64 p0=pack2(a.x,a.x), p1=pack2(a.y,a.y), p2=pack2(a.z,a.z), p3=pack2(a.w,a.w);
                u64 q0=pack2(b.x,b.x), q1=pack2(b.y,b.y), q2=pack2(b.z,b.z), q3=pack2(b.w,b.w);
                aA0 = fma2(mA0.x,p0,aA0); aA0 = fma2(mA0.y,p1,aA0); aA0 = fma2(mB0.x,p2,aA0); aA0 = fma2(mB0.y,p3,aA0);
                aB0 = fma2(mA0.x,q0,aB0); aB0 = fma2(mA0.y,q1,aB0); aB0 = fma2(mB0.x,q2,aB0); aB0 = fma2(mB0.y,q3,aB0);
                aA1 = fma2(mA1.x,p0,aA1); aA1 = fma2(mA1.y,p1,aA1); aA1 = fma2(mB1.x,p2,aA1); aA1 = fma2(mB1.y,p3,aA1);
                aB1 = fma2(mA1.x,q0,aB1); aB1 = fma2(mA1.y,q1,aB1); aB1 = fma2(mB1.x,q2,aB1); aB1 = fma2(mB1.y,q3,aB1);
            }
            unpack2(aA0, vs0[0], vs0[1]); unpack2(aB0, vs1[0], vs1[1]);
            unpack2(aA1, vs0[2], vs0[3]); unpack2(aB1, vs1[2], vs1[3]);
        }
        __syncwarp();
        ((float2*)ebase)[l]        = make_float2(vs0[0], vs0[1]);
        ((float2*)ebase)[32+l]     = make_float2(vs1[0], vs1[1]);
        ((float2*)(ebase+960))[l]    = make_float2(vs0[2], vs0[3]);
        ((float2*)(ebase+960))[32+l] = make_float2(vs1[2], vs1[3]);
        __syncwarp();
        float gate[4];
        {
            u64 aG0 = 0, aG1 = 0;
            const float4* wg = (const float4*)&sWgT[l*68];
            #pragma unroll 4
            for (int j = 0; j < 16; j++) {
                float4 w = wg[j];
                ulonglong2 mA0 = mp0[2*j], mB0 = mp0[2*j+1];
                ulonglong2 mA1 = mp1[2*j], mB1 = mp1[2*j+1];
                u64 p0=pack2(w.x,w.x), p1=pack2(w.y,w.y), p2=pack2(w.z,w.z), p3=pack2(w.w,w.w);
                aG0 = fma2(mA0.x,p0,aG0); aG0 = fma2(mA0.y,p1,aG0); aG0 = fma2(mB0.x,p2,aG0); aG0 = fma2(mB0.y,p3,aG0);
                aG1 = fma2(mA1.x,p0,aG1); aG1 = fma2(mA1.y,p1,aG1); aG1 = fma2(mB1.x,p2,aG1); aG1 = fma2(mB1.y,p3,aG1);
            }
            float gE0,gE1,gE2,gE3;
            unpack2(aG0,gE0,gE1); unpack2(aG1,gE2,gE3);
            gate[0]=sigf(gE0); gate[1]=sigf(gE1); gate[2]=sigf(gE2); gate[3]=sigf(gE3);
        }
        float v0[4], v1[4], v2[4];
        {
            u64 axy[4] = {0,0,0,0}; u64 az0 = 0, az1 = 0;
            const float4* wv = (const float4*)&sWvvT[l*132];
            const ulonglong2* cxA = (const ulonglong2*)(ebase+192);
            const ulonglong2* cxB = (const ulonglong2*)(ebase+448);
            const ulonglong2* cxC = (const ulonglong2*)(ebase+960+192);
            const ulonglong2* cxD = (const ulonglong2*)(ebase+960+448);
            const ulonglong2* czA = (const ulonglong2*)(ebase+704);
            const ulonglong2* czB = (const ulonglong2*)(ebase+960+704);
            #pragma unroll 4
            for (int j = 0; j < 32; j++) {
                float4 w = wv[j];
                u64 p0=pack2(w.x,w.x), p1=pack2(w.y,w.y), p2=pack2(w.z,w.z), p3=pack2(w.w,w.w);
                ulonglong2 a0 = cxA[2*j], a1 = cxA[2*j+1];
                axy[0] = fma2(a0.x,p0,axy[0]); axy[0] = fma2(a0.y,p1,axy[0]);
                axy[0] = fma2(a1.x,p2,axy[0]); axy[0] = fma2(a1.y,p3,axy[0]);
                ulonglong2 b0 = cxB[2*j], b1 = cxB[2*j+1];
                axy[1] = fma2(b0.x,p0,axy[1]); axy[1] = fma2(b0.y,p1,axy[1]);
                axy[1] = fma2(b1.x,p2,axy[1]); axy[1] = fma2(b1.y,p3,axy[1]);
                ulonglong2 c0 = cxC[2*j], c1 = cxC[2*j+1];
                axy[2] = fma2(c0.x,p0,axy[2]); axy[2] = fma2(c0.y,p1,axy[2]);
                axy[2] = fma2(c1.x,p2,axy[2]); axy[2] = fma2(c1.y,p3,axy[2]);
                ulonglong2 d0 = cxD[2*j], d1 = cxD[2*j+1];
                axy[3] = fma2(d0.x,p0,axy[3]); axy[3] = fma2(d0.y,p1,axy[3]);
                axy[3] = fma2(d1.x,p2,axy[3]); axy[3] = fma2(d1.y,p3,axy[3]);
                ulonglong2 z0 = czA[2*j], z1 = czA[2*j+1];
                az0 = fma2(z0.x,p0,az0); az0 = fma2(z0.y,p1,az0);
                az0 = fma2(z1.x,p2,az0); az0 = fma2(z1.y,p3,az0);
                ulonglong2 z2 = czB[2*j], z3 = czB[2*j+1];
                az1 = fma2(z2.x,p0,az1); az1 = fma2(z2.y,p1,az1);
                az1 = fma2(z3.x,p2,az1); az1 = fma2(z3.y,p3,az1);
            }
            #pragma unroll
            for (int u = 0; u < 4; u++) unpack2(axy[u], v0[u], v1[u]);
            unpack2(az0, v2[0], v2[1]); unpack2(az1, v2[2], v2[3]);
        }
        #pragma unroll
        for (int u = 0; u < 4; u++) { v0[u] *= gate[u]; v1[u] *= gate[u]; v2[u] *= gate[u]; }
        __syncwarp();
        #pragma unroll
        for (int pr = 0; pr < 2; pr++) {
            int u0 = 2*pr, u1 = u0+1;
            float* pb = ebase + pr*960;
            float2* Bp  = (float2*)pb;
            float2* Cx0 = (float2*)(pb+192);
            float2* Cx1 = (float2*)(pb+448);
            float2* Czp = (float2*)(pb+704);
            float4 Ya = Y[u0], Yb = Y[u1];
            float ssa = sigf(vs0[u0]), sta = sigf(vs1[u0]);
            float ssb = sigf(vs0[u1]), stb = sigf(vs1[u1]);
            float cax = v1[u0]*Ya.w - v2[u0]*Ya.z, cay = v2[u0]*Ya.y - v0[u0]*Ya.w, caz = v0[u0]*Ya.z - v1[u0]*Ya.y;
            float cbx = v1[u1]*Yb.w - v2[u1]*Yb.z, cby = v2[u1]*Yb.y - v0[u1]*Yb.w, cbz = v0[u1]*Yb.z - v1[u1]*Yb.y;
            Bp[l]    = make_float2(sw2[l]*ssa*Ya.x, sw2[l]*ssb*Yb.x);
            Bp[32+l] = make_float2(sw2[32+l]*sta*Ya.x, sw2[32+l]*stb*Yb.x);
            Bp[64+l] = make_float2(sw2[160+l]*(v0[u0]*Ya.y+v1[u0]*Ya.z+v2[u0]*Ya.w)*ISQ3,
                                   sw2[160+l]*(v0[u1]*Yb.y+v1[u1]*Yb.z+v2[u1]*Yb.w)*ISQ3);
            float g2a = sw2[64+l]*ssa, g3a = sw2[96+l]*sta, g4 = sw2[128+l], g6 = sw2[192+l]*ISQ2;
            float g2b = sw2[64+l]*ssb, g3b = sw2[96+l]*stb;
            Cx0[l]    = make_float2(g2a*Ya.y, g2a*Ya.z);
            Cx0[32+l] = make_float2(g3a*Ya.y, g3a*Ya.z);
            Cx0[64+l] = make_float2(g4*v0[u0]*Ya.x, g4*v1[u0]*Ya.x);
            Cx0[96+l] = make_float2(g6*cax, g6*cay);
            Cx1[l]    = make_float2(g2b*Yb.y, g2b*Yb.z);
            Cx1[32+l] = make_float2(g3b*Yb.y, g3b*Yb.z);
            Cx1[64+l] = make_float2(g4*v0[u1]*Yb.x, g4*v1[u1]*Yb.x);
            Cx1[96+l] = make_float2(g6*cbx, g6*cby);
            Czp[l]    = make_float2(g2a*Ya.w,        g2b*Yb.w);
            Czp[32+l] = make_float2(g3a*Ya.w,        g3b*Yb.w);
            Czp[64+l] = make_float2(g4*v2[u0]*Ya.x,  g4*v2[u1]*Yb.x);
            Czp[96+l] = make_float2(g6*caz,          g6*cbz);
        }
        __syncwarp();
        float hsA[4], hsB[4];
        {
            u64 aA0=0, aB0=0, aA1=0, aB1=0;
            const float4* wa = (const float4*)&sWvlT[l*100];
            const float4* wb = (const float4*)&sWvlT[(32+l)*100];
            #pragma unroll 6
            for (int j = 0; j < 24; j++) {
                float4 a = wa[j], b = wb[j];
                ulonglong2 mA0 = mp0[2*j], mB0 = mp0[2*j+1];
                ulonglong2 mA1 = mp1[2*j], mB1 = mp1[2*j+1];
                u64 p0=pack2(a.x,a.x), p1=pack2(a.y,a.y), p2=pack2(a.z,a.z), p3=pack2(a.w,a.w);
                u64 q0=pack2(b.x,b.x), q1=pack2(b.y,b.y), q2=pack2(b.z,b.z), q3=pack2(b.w,b.w);
                aA0 = fma2(mA0.x,p0,aA0); aA0 = fma2(mA0.y,p1,aA0); aA0 = fma2(mB0.x,p2,aA0); aA0 = fma2(mB0.y,p3,aA0);
                aB0 = fma2(mA0.x,q0,aB0); aB0 = fma2(mA0.y,q1,aB0); aB0 = fma2(mB0.x,q2,aB0); aB0 = fma2(mB0.y,q3,aB0);
                aA1 = fma2(mA1.x,p0,aA1); aA1 = fma2(mA1.y,p1,aA1); aA1 = fma2(mB1.x,p2,aA1); aA1 = fma2(mB1.y,p3,aA1);
                aB1 = fma2(mA1.x,q0,aB1); aB1 = fma2(mA1.y,q1,aB1); aB1 = fma2(mB1.x,q2,aB1); aB1 = fma2(mB1.y,q3,aB1);
            }
            unpack2(aA0, hsA[0], hsA[1]); unpack2(aB0, hsB[0], hsB[1]);
            unpack2(aA1, hsA[2], hsA[3]); unpack2(aB1, hsB[2], hsB[3]);
        }
        float h0[4], h1[4], h2[4];
        {
            u64 axy[4] = {0,0,0,0}; u64 az0 = 0, az1 = 0;
            const float4* wv = (const float4*)&sWvv2T[l*132];
            const ulonglong2* cxA = (const ulonglong2*)(ebase+192);
            const ulonglong2* cxB = (const ulonglong2*)(ebase+448);
            const ulonglong2* cxC = (const ulonglong2*)(ebase+960+192);
            const ulonglong2* cxD = (const ulonglong2*)(ebase+960+448);
            const ulonglong2* czA = (const ulonglong2*)(ebase+704);
            const ulonglong2* czB = (const ulonglong2*)(ebase+960+704);
            #pragma unroll 4
            for (int j = 0; j < 32; j++) {
                float4 w = wv[j];
                u64 p0=pack2(w.x,w.x), p1=pack2(w.y,w.y), p2=pack2(w.z,w.z), p3=pack2(w.w,w.w);
                ulonglong2 a0 = cxA[2*j], a1 = cxA[2*j+1];
                axy[0] = fma2(a0.x,p0,axy[0]); axy[0] = fma2(a0.y,p1,axy[0]);
                axy[0] = fma2(a1.x,p2,axy[0]); axy[0] = fma2(a1.y,p3,axy[0]);
                ulonglong2 b0 = cxB[2*j], b1 = cxB[2*j+1];
                axy[1] = fma2(b0.x,p0,axy[1]); axy[1] = fma2(b0.y,p1,axy[1]);
                axy[1] = fma2(b1.x,p2,axy[1]); axy[1] = fma2(b1.y,p3,axy[1]);
                ulonglong2 c0 = cxC[2*j], c1 = cxC[2*j+1];
                axy[2] = fma2(c0.x,p0,axy[2]); axy[2] = fma2(c0.y,p1,axy[2]);
                axy[2] = fma2(c1.x,p2,axy[2]); axy[2] = fma2(c1.y,p3,axy[2]);
                ulonglong2 d0 = cxD[2*j], d1 = cxD[2*j+1];
                axy[3] = fma2(d0.x,p0,axy[3]); axy[3] = fma2(d0.y,p1,axy[3]);
                axy[3] = fma2(d1.x,p2,axy[3]); axy[3] = fma2(d1.y,p3,axy[3]);
                ulonglong2 z0 = czA[2*j], z1 = czA[2*j+1];
                az0 = fma2(z0.x,p0,az0); az0 = fma2(z0.y,p1,az0);
                az0 = fma2(z1.x,p2,az0); az0 = fma2(z1.y,p3,az0);
                ulonglong2 z2 = czB[2*j], z3 = czB[2*j+1];
                az1 = fma2(z2.x,p0,az1); az1 = fma2(z2.y,p1,az1);
                az1 = fma2(z3.x,p2,az1); az1 = fma2(z3.y,p3,az1);
            }
            #pragma unroll
            for (int u = 0; u < 4; u++) unpack2(axy[u], h0[u], h1[u]);
            unpack2(az0, h2[0], h2[1]); unpack2(az1, h2[2], h2[3]);
        }
        int hA = l >> 4, hV = l >> 3;
        #pragma unroll
        for (int u = 0; u < 4; u++) {
            int e = e0+u, d = dst[u];
            float al0 = g_aex[4*e+hA]   / (g_den[4*d+hA]   + 1e-16f);
            float al1 = g_aex[4*e+2+hA] / (g_den[4*d+2+hA] + 1e-16f);
            float alv = g_aex[4*e+hV]   / (g_den[4*d+hV]   + 1e-16f);
            float* ag = g_agg + (size_t)d*160;
            atomicAdd(ag + hA*40 + (l&15), al0*hsA[u]);
            atomicAdd(ag + (2+hA)*40 + (l&15), al1*hsB[u]);
            int vb = hV*40 + 16 + (l&7)*3;
            atomicAdd(ag+vb,   alv*h0[u]);
            atomicAdd(ag+vb+1, alv*h1[u]);
            atomicAdd(ag+vb+2, alv*h2[u]);
        }
        __syncwarp();
    }
}

// ---- output projection + residual: persistent, weights cached in smem ----
__global__ void __launch_bounds__(512) k_out(
    const float* __restrict__ node, const float* __restrict__ Wps,
    const float* __restrict__ Wpv, float* __restrict__ out)
{
    __shared__ float sw[5120];   // Wps 4096 | Wpv 1024
    float* sWps = sw; float* sWpv = sw+4096;
    int tid = threadIdx.x;
    for (int i = tid; i < 4096; i += 512) sWps[i] = Wps[i];
    for (int i = tid; i < 1024; i += 512) sWpv[i] = Wpv[i];
    __syncthreads();
    int l = tid & 31, wid = tid >> 5;
    int tw = gridDim.x*16;
    for (int w = blockIdx.x*16 + wid; w < NN; w += tw) {
        const float* ag = g_agg + (size_t)w*160;
        float a0 = ag[(l>>4)*40 + (l&15)];
        float a1 = ag[(2+(l>>4))*40 + (l&15)];
        int vb = (l>>3)*40 + 16 + (l&7)*3;
        float vx = ag[vb], vy = ag[vb+1], vz = ag[vb+2];
        float s0 = 0.f, s1 = 0.f;
        for (int c = 0; c < 32; c++) {
            float b = __shfl_sync(~0u, a0, c);
            s0 += b*sWps[c*64+l]; s1 += b*sWps[c*64+32+l];
        }
        for (int c = 0; c < 32; c++) {
            float b = __shfl_sync(~0u, a1, c);
            s0 += b*sWps[(c+32)*64+l]; s1 += b*sWps[(c+32)*64+32+l];
        }
        float o0 = 0.f, o1 = 0.f, o2 = 0.f;
        for (int c = 0; c < 32; c++) {
            float ww = sWpv[c*32+l];
            o0 += __shfl_sync(~0u, vx, c)*ww;
            o1 += __shfl_sync(~0u, vy, c)*ww;
            o2 += __shfl_sync(~0u, vz, c)*ww;
        }
        const float* nr = node + (size_t)w*160;
        float* orow = out + (size_t)w*160;
        orow[l] = nr[l] + s0;
        orow[32+l] = nr[32+l] + s1;
        orow[64+3*l] = nr[64+3*l] + o0;
        orow[65+3*l] = nr[65+3*l] + o1;
        orow[66+3*l] = nr[66+3*l] + o2;
    }
}

extern "C" void kernel_launch(void* const* d_in, const int* in_sizes, int n_in,
                              void* d_out, int out_size) {
    int ei_pos = -1;
    for (int i = 0; i < n_in; i++) if (in_sizes[i] == 2*EE) { ei_pos = i; break; }
    const float* p[25]; int j = 0;
    for (int i = 0; i < n_in; i++) { if (i == ei_pos) continue; p[j++] = (const float*)d_in[i]; }
    const float *node = p[0], *rbf = p[1], *rsh = p[2], *gs = p[3], *bs = p[4], *gv = p[5],
                *WsS = p[6], *WvS = p[7], *WsD = p[8], *WvD = p[9], *Wr = p[10],
                *Wa = p[11], *ad = p[12], *Wval = p[13], *Wvv = p[14], *Wg = p[15],
                *w2ss = p[16], *w2sv = p[17], *w2vs = p[18], *w2v0 = p[19], *w2v1 = p[20],
                *Wvl = p[21], *Wvv2 = p[22], *Wps = p[23], *Wpv = p[24];
    const int* ei = (const int*)d_in[ei_pos];
    float* out = (float*)d_out;

    cudaFuncSetAttribute(k_edge1, cudaFuncAttributeMaxDynamicSharedMemorySize, 23104*4);
    cudaFuncSetAttribute(k_edge2, cudaFuncAttributeMaxDynamicSharedMemorySize, 55008*4);

    k_init<<<256, 256>>>();
    k_node<<<148, 512>>>(node, gs, bs, gv, WsS, WvS, WsD, WvD);
    k_edge1<<<148, 512, 23104*4>>>(ei, rbf, rsh, Wr, Wa, ad);
    k_soft<<<(EE*4 + 255)/256, 256>>>(ei);
    k_edge2<<<148, 448, 55008*4>>>(ei, rbf, rsh, Wr, Wval, Wvv, Wg,
                                   w2ss, w2sv, w2vs, w2v0, w2v1, Wvl, Wvv2);
    k_out<<<148, 512>>>(node, Wps, Wpv, out);
}